// round 2
// baseline (speedup 1.0000x reference)
#include <cuda_runtime.h>
#include <float.h>

#define NB   32
#define DX   128
#define DY   128
#define DZ   64
#define KTOP 10
#define YT   16
#define XT   64
#define BY   (DY / YT)        // 8
#define BX   (DX / XT)        // 2
#define NBLK (BY * BX)        // 16 blocks per batch

// Per-(batch, block) top-10 keys; every slot overwritten each launch.
__device__ unsigned long long gBlockTop[NB][NBLK][KTOP];

__device__ __forceinline__ float4 fmax4(float4 a, float4 b) {
    return make_float4(fmaxf(a.x, b.x), fmaxf(a.y, b.y),
                       fmaxf(a.z, b.z), fmaxf(a.w, b.w));
}

__device__ __forceinline__ void cp_async16(void* sdst, const void* gsrc, bool p) {
    unsigned s = (unsigned)__cvta_generic_to_shared(sdst);
    int sz = p ? 16 : 0;
    asm volatile("cp.async.cg.shared.global [%0], [%1], 16, %2;\n"
                 :: "r"(s), "l"(gsrc), "r"(sz));
}
#define CP_COMMIT() asm volatile("cp.async.commit_group;\n")
#define CP_WAIT2()  asm volatile("cp.async.wait_group 2;\n" ::: "memory")

// Shared 10-slot replace-min insert via CAS (cold path: block merge only).
__device__ __forceinline__ void insert_topk_sh(unsigned long long* slots,
                                               unsigned long long key) {
    for (;;) {
        int mi = 0;
        unsigned long long mv = slots[0];
#pragma unroll
        for (int i = 1; i < KTOP; i++) {
            unsigned long long v = slots[i];
            if (v < mv) { mv = v; mi = i; }
        }
        if (key <= mv) return;
        if (atomicCAS(&slots[mi], mv, key) == mv) return;
    }
}

__global__ __launch_bounds__(256)
void peaks_kernel(const float* __restrict__ in) {
    __shared__ float4 buf[3][YT + 2][DZ / 4];            // 13.8 KB, triple buffer
    __shared__ unsigned long long lists[256][KTOP];      // 20 KB per-thread top-10
    __shared__ unsigned long long sTop[KTOP];

    const int tid = threadIdx.x;
    const int tx = tid & 15;          // z chunk (float4)
    const int ty = tid >> 4;          // output row in tile
    const int b  = blockIdx.z;
    const int y0 = blockIdx.x * YT;
    const int x0 = blockIdx.y * XT;

    const float4* in4 = (const float4*)in + (size_t)b * DX * DY * (DZ / 4);

#pragma unroll
    for (int i = 0; i < KTOP; i++) lists[tid][i] = 0ULL;
    if (tid < KTOP) sTop[tid] = 0ULL;

    // issue cp.async for one (YT+2)x(DZ) plane; OOB -> zero-fill (input >= 0
    // so zero padding never changes peak decisions for positive values)
    auto issue_plane = [&](int xp, int slot) {
        const bool xin = (xp >= 0 && xp < DX);
        {
            int r = tid >> 4, zc = tid & 15;
            int gy = y0 - 1 + r;
            bool v = xin && gy >= 0 && gy < DY;
            const float4* src = v ? in4 + ((size_t)xp * DY + gy) * (DZ / 4) + zc : in4;
            cp_async16(&buf[slot][r][zc], src, v);
        }
        if (tid < 32) {
            int i = 256 + tid;
            int r = i >> 4, zc = i & 15;
            int gy = y0 - 1 + r;
            bool v = xin && gy >= 0 && gy < DY;
            const float4* src = v ? in4 + ((size_t)xp * DY + gy) * (DZ / 4) + zc : in4;
            cp_async16(&buf[slot][r][zc], src, v);
        }
        CP_COMMIT();
    };

    issue_plane(x0 - 1, 0);
    issue_plane(x0,     1);

    const float4 NEG = make_float4(-FLT_MAX, -FLT_MAX, -FLT_MAX, -FLT_MAX);
    float4 yz0 = NEG, yz1 = NEG, yz2 = NEG, rawc = NEG;
    unsigned long long kmin = 0ULL;

    auto check = [&](float v, float m, unsigned flat) {
        if (v > 0.0f && v == m) {
            unsigned long long key =
                ((unsigned long long)__float_as_uint(v) << 32) |
                (unsigned long long)(~flat);
            if (key > kmin) {
                unsigned long long mv = lists[tid][0];
                int mi = 0;
#pragma unroll
                for (int i = 1; i < KTOP; i++) {
                    unsigned long long t = lists[tid][i];
                    if (t < mv) { mv = t; mi = i; }
                }
                lists[tid][mi] = key;
                unsigned long long nm = key;
#pragma unroll
                for (int i = 0; i < KTOP; i++) {
                    unsigned long long t = lists[tid][i];
                    if (t < nm) nm = t;
                }
                kmin = nm;
            }
        }
    };

    for (int cnt = 0; cnt < XT + 2; cnt++) {
        const int xp = x0 - 1 + cnt;

        if (cnt + 1 < XT + 2) issue_plane(xp + 1, (cnt + 1) % 3);
        else                  CP_COMMIT();       // keep group count aligned
        CP_WAIT2();                              // plane xp's group complete
        __syncthreads();                         // all threads' copies visible;
                                                 // also protects buffer reuse (dist 3)
        const int s = cnt % 3;

        // fused z-window + y-window max around output row (ty) at plane xp
        float4 nyz;
        {
            float4 zr[3];
#pragma unroll
            for (int k = 0; k < 3; k++) {
                const int r = ty + k;
                float4 c = buf[s][r][tx];
                float l  = (tx > 0)  ? buf[s][r][tx - 1].w : -FLT_MAX;
                float rr = (tx < 15) ? buf[s][r][tx + 1].x : -FLT_MAX;
                zr[k].x = fmaxf(fmaxf(l,   c.x), c.y);
                zr[k].y = fmaxf(fmaxf(c.x, c.y), c.z);
                zr[k].z = fmaxf(fmaxf(c.y, c.z), c.w);
                zr[k].w = fmaxf(fmaxf(c.z, c.w), rr);
            }
            nyz = fmax4(zr[0], fmax4(zr[1], zr[2]));
        }
        float4 nraw = buf[s][ty + 1][tx];

        yz0 = yz1; yz1 = yz2; yz2 = nyz;

        if (cnt >= 2) {
            const int xc = xp - 1;
            float4 m = fmax4(yz0, fmax4(yz1, yz2));
            float4 c = rawc;                     // raw center of plane xc
            const int gy = y0 + ty;
            const unsigned base = (unsigned)((xc * DY + gy) * DZ + tx * 4);
            check(c.x, m.x, base + 0);
            check(c.y, m.y, base + 1);
            check(c.z, m.z, base + 2);
            check(c.w, m.w, base + 3);
        }
        rawc = nraw;
    }

    __syncthreads();
    // block merge: fold 256 per-thread lists into sTop (cold, CAS mostly rejects)
#pragma unroll
    for (int i = 0; i < KTOP; i++) {
        unsigned long long key = lists[tid][i];
        if (key) insert_topk_sh(sTop, key);
    }
    __syncthreads();
    if (tid < KTOP)
        gBlockTop[b][blockIdx.y * BY + blockIdx.x][tid] = sTop[tid];
}

__global__ void finalize_kernel(float* __restrict__ out) {
    int b = threadIdx.x;
    if (b >= NB) return;

    unsigned long long k[KTOP];
#pragma unroll
    for (int i = 0; i < KTOP; i++) k[i] = 0ULL;

    const unsigned long long* src = &gBlockTop[b][0][0];
    unsigned long long kmin = 0ULL;
    for (int i = 0; i < NBLK * KTOP; i++) {
        unsigned long long key = src[i];
        if (key > kmin) {
            int mi = 0;
            for (int j = 1; j < KTOP; j++) if (k[j] < k[mi]) mi = j;
            k[mi] = key;
            kmin = k[0];
            for (int j = 1; j < KTOP; j++) if (k[j] < kmin) kmin = k[j];
        }
    }

    // selection sort descending (matches top_k order incl. index tie-break)
    for (int i = 0; i < KTOP; i++) {
        int mi = i;
        for (int j = i + 1; j < KTOP; j++) if (k[j] > k[mi]) mi = j;
        unsigned long long t = k[i]; k[i] = k[mi]; k[mi] = t;
    }

    float* o = out + (size_t)b * KTOP * 5;
    for (int i = 0; i < KTOP; i++) {
        float v = __uint_as_float((unsigned)(k[i] >> 32));
        unsigned idx = ~(unsigned)(k[i] & 0xFFFFFFFFull);
        int ix = (int)(idx / (DY * DZ));
        int iy = (int)((idx / DZ) % DY);
        int iz = (int)(idx % DZ);
        float lx = ((float)ix / 127.0f) * 8000.0f - 4000.0f;
        float ly = ((float)iy / 127.0f) * 8000.0f - 4000.0f;
        float lz = ((float)iz / 63.0f)  * 2000.0f - 700.0f;
        float conf = (v > 0.3f) ? 0.0f : -1.0f;
        o[i * 5 + 0] = lx;
        o[i * 5 + 1] = ly;
        o[i * 5 + 2] = lz;
        o[i * 5 + 3] = conf;
        o[i * 5 + 4] = v;
    }
}

extern "C" void kernel_launch(void* const* d_in, const int* in_sizes, int n_in,
                              void* d_out, int out_size) {
    const float* in = (const float*)d_in[0];
    float* out = (float*)d_out;

    dim3 grid(BY, BX, NB);            // (8, 2, 32) = 512 blocks
    peaks_kernel<<<grid, 256>>>(in);
    finalize_kernel<<<1, 32>>>(out);
}

// round 3
// speedup vs baseline: 1.4259x; 1.4259x over previous
#include <cuda_runtime.h>
#include <float.h>

#define NB   32
#define DX   128
#define DY   128
#define DZ   64
#define KTOP 10
#define DEPTH 6          // plane ring depth per warp
#define NBLK 8           // blocks per batch (4 y-blocks * 2 x-halves)

// Per-(batch, block) top-10 keys; every slot overwritten each launch.
__device__ unsigned long long gBlockTop[NB][NBLK][KTOP];

__device__ __forceinline__ float4 fmax4(float4 a, float4 b) {
    return make_float4(fmaxf(a.x, b.x), fmaxf(a.y, b.y),
                       fmaxf(a.z, b.z), fmaxf(a.w, b.w));
}

__device__ __forceinline__ void cp_async16(void* sdst, const void* gsrc, bool p) {
    unsigned s = (unsigned)__cvta_generic_to_shared(sdst);
    int sz = p ? 16 : 0;
    asm volatile("cp.async.cg.shared.global [%0], [%1], 16, %2;\n"
                 :: "r"(s), "l"(gsrc), "r"(sz));
}
#define CP_COMMIT() asm volatile("cp.async.commit_group;\n")
#define CP_WAIT3()  asm volatile("cp.async.wait_group 3;\n" ::: "memory")

// Shared 10-slot replace-min insert via CAS (cold path: end-of-kernel merge).
__device__ __forceinline__ void insert_topk_sh(unsigned long long* slots,
                                               unsigned long long key) {
    for (;;) {
        int mi = 0;
        unsigned long long mv = slots[0];
#pragma unroll
        for (int i = 1; i < KTOP; i++) {
            unsigned long long v = slots[i];
            if (v < mv) { mv = v; mi = i; }
        }
        if (key <= mv) return;
        if (atomicCAS(&slots[mi], mv, key) == mv) return;
    }
}

__global__ __launch_bounds__(256)
void peaks_kernel(const float* __restrict__ in) {
    // Per-warp private plane ring: [warp][slot][row 0..5][z-chunk 0..15]
    __shared__ float4 buf[8][DEPTH][6][16];                 // 72 KB
    __shared__ unsigned long long lists[KTOP][256];         // 20 KB, slot-major
    __shared__ unsigned long long sTop[KTOP];

    const int tid  = threadIdx.x;
    const int w    = tid >> 5;
    const int lane = tid & 31;
    const int lr0  = lane >> 4;      // 0..1: base row of this lane's items
    const int lzc  = lane & 15;      // z chunk (float4)

    const int b  = blockIdx.z;
    const int yg = blockIdx.x * 8 + w;     // y-group 0..31 (4 rows each)
    const int yb = yg * 4;
    const int x0 = blockIdx.y * 64;        // x-half base

    const float4* in4 = (const float4*)in + (size_t)b * DX * DY * (DZ / 4);

#pragma unroll
    for (int i = 0; i < KTOP; i++) lists[i][tid] = 0ULL;
    if (tid < KTOP) sTop[tid] = 0ULL;
    __syncthreads();                       // once, before the stream loop

    // Issue one warp-private plane (6 rows x 64 z) = 3 cp.asyncs per lane.
    auto issue_plane = [&](int xp, int slot) {
        const bool xin = (xp >= 0 && xp < DX);
        const unsigned pbase = (unsigned)xp * (DY * DZ / 4);
#pragma unroll
        for (int k = 0; k < 3; k++) {
            int r  = lr0 + 2 * k;          // 0..5
            int gy = yb - 1 + r;
            bool v = xin && gy >= 0 && gy < DY;
            const float4* src = v ? in4 + pbase + (unsigned)gy * (DZ / 4) + lzc
                                  : in4;
            cp_async16(&buf[w][slot][r][lzc], src, v);
        }
        CP_COMMIT();
    };

    issue_plane(x0 - 1, 0);
    issue_plane(x0,     1);
    issue_plane(x0 + 1, 2);

    const float4 NEG = make_float4(-FLT_MAX, -FLT_MAX, -FLT_MAX, -FLT_MAX);
    float4 yz[2][3];
#pragma unroll
    for (int p = 0; p < 2; p++) { yz[p][0] = NEG; yz[p][1] = NEG; yz[p][2] = NEG; }
    unsigned long long kmin = 0ULL;

    auto check = [&](float v, float m, unsigned flat) {
        if (v > 0.0f && v == m) {
            unsigned long long key =
                ((unsigned long long)__float_as_uint(v) << 32) |
                (unsigned long long)(~flat);
            if (key > kmin) {
                unsigned long long mv = lists[0][tid];
                int mi = 0;
#pragma unroll
                for (int i = 1; i < KTOP; i++) {
                    unsigned long long t = lists[i][tid];
                    if (t < mv) { mv = t; mi = i; }
                }
                lists[mi][tid] = key;
                unsigned long long nm = key;
#pragma unroll
                for (int i = 0; i < KTOP; i++) {
                    unsigned long long t = lists[i][tid];
                    if (t < nm) nm = t;
                }
                kmin = nm;
            }
        }
    };

    for (int cnt = 0; cnt < 66; cnt++) {
        if (cnt + 3 < 66) issue_plane(x0 - 1 + cnt + 3, (cnt + 3) % DEPTH);
        else              CP_COMMIT();          // keep group accounting aligned
        CP_WAIT3();                             // this warp's plane cnt complete
        __syncwarp();                           // peer-lane smem visibility

        const int sc = cnt % DEPTH;
        const float4 (*P)[16] = buf[w][sc];

        // fused z+y window max for this lane's 2 positions at plane cnt
#pragma unroll
        for (int p = 0; p < 2; p++) {
            const int ro = lr0 + 2 * p;         // output-position row 0..3
            float4 zr[3];
#pragma unroll
            for (int dk = 0; dk < 3; dk++) {
                const int r = ro + dk;
                float4 c = P[r][lzc];
                float l  = (lzc > 0)  ? P[r][lzc - 1].w : -FLT_MAX;
                float rr = (lzc < 15) ? P[r][lzc + 1].x : -FLT_MAX;
                zr[dk].x = fmaxf(fmaxf(l,   c.x), c.y);
                zr[dk].y = fmaxf(fmaxf(c.x, c.y), c.z);
                zr[dk].z = fmaxf(fmaxf(c.y, c.z), c.w);
                zr[dk].w = fmaxf(fmaxf(c.z, c.w), rr);
            }
            float4 nyz = fmax4(zr[0], fmax4(zr[1], zr[2]));
            yz[p][0] = yz[p][1]; yz[p][1] = yz[p][2]; yz[p][2] = nyz;
        }

        if (cnt >= 2) {
            const int xc = x0 + cnt - 2;        // output plane
            const int sr = (cnt - 1) % DEPTH;   // raw center plane's slot
#pragma unroll
            for (int p = 0; p < 2; p++) {
                const int ro = lr0 + 2 * p;
                float4 m = fmax4(yz[p][0], fmax4(yz[p][1], yz[p][2]));
                float4 c = buf[w][sr][ro + 1][lzc];
                const int gy = yb + ro;
                const unsigned base = (unsigned)((xc * DY + gy) * DZ + lzc * 4);
                check(c.x, m.x, base + 0);
                check(c.y, m.y, base + 1);
                check(c.z, m.z, base + 2);
                check(c.w, m.w, base + 3);
            }
        }
    }

    __syncthreads();
#pragma unroll
    for (int i = 0; i < KTOP; i++) {
        unsigned long long key = lists[i][tid];
        if (key) insert_topk_sh(sTop, key);
    }
    __syncthreads();
    if (tid < KTOP)
        gBlockTop[b][blockIdx.y * 4 + blockIdx.x][tid] = sTop[tid];
}

// One warp per batch: 10 rounds of warp-shuffle argmax over 80 candidate keys.
__global__ __launch_bounds__(NB * 32)
void finalize_kernel(float* __restrict__ out) {
    const int b    = threadIdx.x >> 5;
    const int lane = threadIdx.x & 31;

    const unsigned long long* src = &gBlockTop[b][0][0];   // 80 keys
    unsigned long long r0 = src[lane];
    unsigned long long r1 = src[32 + lane];
    unsigned long long r2 = (lane < 16) ? src[64 + lane] : 0ULL;

    float* o = out + (size_t)b * KTOP * 5;

#pragma unroll
    for (int round = 0; round < KTOP; round++) {
        unsigned long long m = r0 > r1 ? r0 : r1;
        if (r2 > m) m = r2;
#pragma unroll
        for (int off = 16; off > 0; off >>= 1) {
            unsigned long long t = __shfl_xor_sync(0xFFFFFFFFu, m, off);
            if (t > m) m = t;
        }
        // invalidate winner (keys encode unique voxel indices -> unique)
        if (r0 == m)      r0 = 0ULL;
        else if (r1 == m) r1 = 0ULL;
        else if (r2 == m) r2 = 0ULL;

        if (lane == 0) {
            float v = __uint_as_float((unsigned)(m >> 32));
            unsigned idx = ~(unsigned)(m & 0xFFFFFFFFull);
            int ix = (int)(idx / (DY * DZ));
            int iy = (int)((idx / DZ) % DY);
            int iz = (int)(idx % DZ);
            o[round * 5 + 0] = ((float)ix / 127.0f) * 8000.0f - 4000.0f;
            o[round * 5 + 1] = ((float)iy / 127.0f) * 8000.0f - 4000.0f;
            o[round * 5 + 2] = ((float)iz / 63.0f)  * 2000.0f - 700.0f;
            o[round * 5 + 3] = (v > 0.3f) ? 0.0f : -1.0f;
            o[round * 5 + 4] = v;
        }
    }
}

extern "C" void kernel_launch(void* const* d_in, const int* in_sizes, int n_in,
                              void* d_out, int out_size) {
    const float* in = (const float*)d_in[0];
    float* out = (float*)d_out;

    dim3 grid(4, 2, NB);               // 256 blocks, 8 independent warps each
    peaks_kernel<<<grid, 256>>>(in);
    finalize_kernel<<<1, NB * 32>>>(out);
}

// round 5
// speedup vs baseline: 1.5384x; 1.0789x over previous
#include <cuda_runtime.h>
#include <float.h>

#define NB   32
#define DX   128
#define DY   128
#define DZ   64
#define KTOP 10
#define NBLK 8           // blocks per batch
#define FULLM 0xFFFFFFFFu

// Per-(batch, block) top-10 keys; every slot overwritten each launch.
__device__ unsigned long long gBlockTop[NB][NBLK][KTOP];

__device__ __forceinline__ float2 fmax2(float2 a, float2 b) {
    return make_float2(fmaxf(a.x, b.x), fmaxf(a.y, b.y));
}

// Shared 10-slot replace-min insert via CAS (cold path: end-of-kernel merge).
__device__ __forceinline__ void insert_topk_sh(unsigned long long* slots,
                                               unsigned long long key) {
    for (;;) {
        int mi = 0;
        unsigned long long mv = slots[0];
#pragma unroll
        for (int i = 1; i < KTOP; i++) {
            unsigned long long v = slots[i];
            if (v < mv) { mv = v; mi = i; }
        }
        if (key <= mv) return;
        if (atomicCAS(&slots[mi], mv, key) == mv) return;
    }
}

__global__ __launch_bounds__(256, 2)
void peaks_kernel(const float* __restrict__ in) {
    __shared__ unsigned long long lists[KTOP][256];   // per-thread top-10
    __shared__ unsigned long long sTop[KTOP];

    const int tid  = threadIdx.x;
    const int w    = tid >> 5;
    const int lane = tid & 31;            // z-pair index: z = {2*lane, 2*lane+1}

    const int b  = blockIdx.z;
    const int yg = blockIdx.x * 4 + (w & 3);   // y-group 0..31 (4 rows each)
    const int y0 = yg * 4;
    const int x0 = (w >> 2) * 64;              // x-half base

#pragma unroll
    for (int i = 0; i < KTOP; i++) lists[i][tid] = 0ULL;
    if (tid < KTOP) sTop[tid] = 0ULL;
    __syncthreads();

    const float* base = in + (size_t)b * DX * DY * DZ + 2 * lane;

    const float2 NEG = make_float2(-FLT_MAX, -FLT_MAX);
    auto loadrow = [&](int xp, int gy) -> float2 {
        if (xp >= 0 && xp < DX && gy >= 0 && gy < DY)
            return *(const float2*)(base + ((size_t)xp * DY + gy) * DZ);
        return NEG;
    };

    float2 cur[6], nxt[6];
#pragma unroll
    for (int r = 0; r < 6; r++) cur[r] = loadrow(x0 - 1, y0 - 1 + r);
#pragma unroll
    for (int r = 0; r < 6; r++) nxt[r] = loadrow(x0,     y0 - 1 + r);

    float2 ymA[4], ymB[4], rawc[4];
#pragma unroll
    for (int r = 0; r < 4; r++) { ymA[r] = NEG; ymB[r] = NEG; rawc[r] = NEG; }

    unsigned long long kmin = 0ULL;
    auto check = [&](float v, float m, unsigned flat) {
        if (v == m) {                      // local max (v > halo -inf always)
            unsigned long long key =
                ((unsigned long long)__float_as_uint(v) << 32) |
                (unsigned long long)(~flat);
            if (key > kmin) {
                unsigned long long mv = lists[0][tid];
                int mi = 0;
#pragma unroll
                for (int i = 1; i < KTOP; i++) {
                    unsigned long long t = lists[i][tid];
                    if (t < mv) { mv = t; mi = i; }
                }
                lists[mi][tid] = key;
                unsigned long long nm = key;
#pragma unroll
                for (int i = 0; i < KTOP; i++) {
                    unsigned long long t = lists[i][tid];
                    if (t < nm) nm = t;
                }
                kmin = nm;
            }
        }
    };

    for (int cnt = 0; cnt < 66; cnt++) {
        const int xp = x0 - 1 + cnt;       // plane held in cur

        // ---- z-window max per loaded row (shuffle for z-neighbors) ----
        float2 zm[6];
#pragma unroll
        for (int r = 0; r < 6; r++) {
            float2 c = cur[r];
            float lft = __shfl_up_sync(FULLM, c.y, 1);
            float rgt = __shfl_down_sync(FULLM, c.x, 1);
            if (lane == 0)  lft = -FLT_MAX;
            if (lane == 31) rgt = -FLT_MAX;
            zm[r].x = fmaxf(fmaxf(lft, c.x), c.y);
            zm[r].y = fmaxf(fmaxf(c.x, c.y), rgt);
        }
        // ---- y-window max for the 4 output rows ----
        float2 ymC[4];
#pragma unroll
        for (int r = 0; r < 4; r++)
            ymC[r] = fmax2(zm[r], fmax2(zm[r + 1], zm[r + 2]));

        // ---- output plane xc = xp-1 ----
        if (cnt >= 2) {
            const int xc = xp - 1;
#pragma unroll
            for (int r = 0; r < 4; r++) {
                float2 m = fmax2(ymA[r], fmax2(ymB[r], ymC[r]));
                float2 c = rawc[r];
                const int gy = y0 + r;
                const unsigned fb = (unsigned)((xc * DY + gy) * DZ + 2 * lane);
                check(c.x, m.x, fb);
                check(c.y, m.y, fb + 1);
            }
        }

        // ---- shift history, rotate buffers, prefetch plane xp+2 ----
#pragma unroll
        for (int r = 0; r < 4; r++) {
            ymA[r] = ymB[r];
            ymB[r] = ymC[r];
            rawc[r] = cur[r + 1];          // raw center rows of plane xp
        }
#pragma unroll
        for (int r = 0; r < 6; r++) cur[r] = nxt[r];
#pragma unroll
        for (int r = 0; r < 6; r++) nxt[r] = loadrow(xp + 2, y0 - 1 + r);
    }

    __syncthreads();
#pragma unroll
    for (int i = 0; i < KTOP; i++) {
        unsigned long long key = lists[i][tid];
        if (key) insert_topk_sh(sTop, key);
    }
    __syncthreads();
    if (tid < KTOP)
        gBlockTop[b][blockIdx.x][tid] = sTop[tid];
}

// One warp per batch: 10 rounds of warp-shuffle argmax over 80 candidate keys.
__global__ __launch_bounds__(NB * 32)
void finalize_kernel(float* __restrict__ out) {
    const int b    = threadIdx.x >> 5;
    const int lane = threadIdx.x & 31;

    const unsigned long long* src = &gBlockTop[b][0][0];   // 80 keys
    unsigned long long r0 = src[lane];
    unsigned long long r1 = src[32 + lane];
    unsigned long long r2 = (lane < 16) ? src[64 + lane] : 0ULL;

    float* o = out + (size_t)b * KTOP * 5;

#pragma unroll
    for (int round = 0; round < KTOP; round++) {
        unsigned long long m = r0 > r1 ? r0 : r1;
        if (r2 > m) m = r2;
#pragma unroll
        for (int off = 16; off > 0; off >>= 1) {
            unsigned long long t = __shfl_xor_sync(FULLM, m, off);
            if (t > m) m = t;
        }
        if (r0 == m)      r0 = 0ULL;       // keys unique (encode voxel index)
        else if (r1 == m) r1 = 0ULL;
        else if (r2 == m) r2 = 0ULL;

        if (lane == 0) {
            float v = __uint_as_float((unsigned)(m >> 32));
            unsigned idx = ~(unsigned)(m & 0xFFFFFFFFull);
            int ix = (int)(idx / (DY * DZ));
            int iy = (int)((idx / DZ) % DY);
            int iz = (int)(idx % DZ);
            o[round * 5 + 0] = ((float)ix / 127.0f) * 8000.0f - 4000.0f;
            o[round * 5 + 1] = ((float)iy / 127.0f) * 8000.0f - 4000.0f;
            o[round * 5 + 2] = ((float)iz / 63.0f)  * 2000.0f - 700.0f;
            o[round * 5 + 3] = (v > 0.3f) ? 0.0f : -1.0f;
            o[round * 5 + 4] = v;
        }
    }
}

extern "C" void kernel_launch(void* const* d_in, const int* in_sizes, int n_in,
                              void* d_out, int out_size) {
    const float* in = (const float*)d_in[0];
    float* out = (float*)d_out;

    dim3 grid(NBLK, 1, NB);            // 256 blocks x 8 autonomous warps
    peaks_kernel<<<grid, 256>>>(in);
    finalize_kernel<<<1, NB * 32>>>(out);
}

// round 6
// speedup vs baseline: 1.9179x; 1.2467x over previous
#include <cuda_runtime.h>
#include <float.h>

#define NB   32
#define DX   128
#define DY   128
#define DZ   64
#define KTOP 10
#define NBLK 16          // blocks per batch (4 y-block-groups * 4 x-quarters)
#define FULLM 0xFFFFFFFFu

typedef unsigned long long ull;

// Per-(batch, block) top-10 keys; every slot overwritten each launch.
__device__ ull gBlockTop[NB][NBLK][KTOP];

__device__ __forceinline__ float2 fmax2(float2 a, float2 b) {
    return make_float2(fmaxf(a.x, b.x), fmaxf(a.y, b.y));
}

// Shared 10-slot replace-min insert via CAS. Returns false if rejected
// (key <= current min) so sorted callers can early-out.
__device__ __forceinline__ bool insert_topk_sh(ull* slots, ull key) {
    for (;;) {
        int mi = 0;
        ull mv = slots[0];
#pragma unroll
        for (int i = 1; i < KTOP; i++) {
            ull v = slots[i];
            if (v < mv) { mv = v; mi = i; }
        }
        if (key <= mv) return false;
        if (atomicCAS(&slots[mi], mv, key) == mv) return true;
    }
}

__global__ __launch_bounds__(256, 2)
void peaks_kernel(const float* __restrict__ in) {
    __shared__ ull sTop[KTOP];

    const int tid  = threadIdx.x;
    const int w    = tid >> 5;
    const int lane = tid & 31;            // z-pair: z = {2*lane, 2*lane+1}

    const int b  = blockIdx.z;
    const int xq = blockIdx.x >> 2;                 // x-quarter 0..3
    const int yg = (blockIdx.x & 3) * 8 + w;        // y-group 0..31
    const int y0 = yg * 4;
    const int x0 = xq * 32;

    if (tid < KTOP) sTop[tid] = 0ULL;

    const float* base = in + (size_t)b * DX * DY * DZ + 2 * lane;

    const float2 NEG = make_float2(-FLT_MAX, -FLT_MAX);
    auto loadrow = [&](int xp, int gy) -> float2 {
        if (xp >= 0 && xp < DX && gy >= 0 && gy < DY)
            return *(const float2*)(base + ((size_t)xp * DY + gy) * DZ);
        return NEG;
    };

    float2 cur[6], nxt[6];
#pragma unroll
    for (int r = 0; r < 6; r++) cur[r] = loadrow(x0 - 1, y0 - 1 + r);
#pragma unroll
    for (int r = 0; r < 6; r++) nxt[r] = loadrow(x0,     y0 - 1 + r);

    float2 ymA[4], ymB[4], rawc[4];
#pragma unroll
    for (int r = 0; r < 4; r++) { ymA[r] = NEG; ymB[r] = NEG; rawc[r] = NEG; }

    // Register-resident sorted top-10 (descending). No smem in hot loop.
    ull t[KTOP];
#pragma unroll
    for (int i = 0; i < KTOP; i++) t[i] = 0ULL;

    auto check = [&](float v, float m, unsigned flat) {
        if (v == m) {
            ull key = ((ull)__float_as_uint(v) << 32) | (ull)(~flat);
            if (key > t[KTOP - 1]) {
                t[KTOP - 1] = key;
#pragma unroll
                for (int i = KTOP - 1; i > 0; i--) {
                    ull a = t[i - 1], c = t[i];
                    t[i - 1] = a > c ? a : c;
                    t[i]     = a > c ? c : a;
                }
            }
        }
    };

    for (int cnt = 0; cnt < 34; cnt++) {
        const int xp = x0 - 1 + cnt;      // plane held in cur

        // ---- z-window max per loaded row (shuffles for z-neighbors) ----
        float2 zm[6];
#pragma unroll
        for (int r = 0; r < 6; r++) {
            float2 c = cur[r];
            float lft = __shfl_up_sync(FULLM, c.y, 1);
            float rgt = __shfl_down_sync(FULLM, c.x, 1);
            if (lane == 0)  lft = -FLT_MAX;
            if (lane == 31) rgt = -FLT_MAX;
            zm[r].x = fmaxf(fmaxf(lft, c.x), c.y);
            zm[r].y = fmaxf(fmaxf(c.x, c.y), rgt);
        }
        // ---- y-window max for the 4 output rows ----
        float2 ymC[4];
#pragma unroll
        for (int r = 0; r < 4; r++)
            ymC[r] = fmax2(zm[r], fmax2(zm[r + 1], zm[r + 2]));

        // ---- output plane xc = xp-1 ----
        if (cnt >= 2) {
            const int xc = xp - 1;
#pragma unroll
            for (int r = 0; r < 4; r++) {
                float2 m = fmax2(ymA[r], fmax2(ymB[r], ymC[r]));
                float2 c = rawc[r];
                const int gy = y0 + r;
                const unsigned fb = (unsigned)((xc * DY + gy) * DZ + 2 * lane);
                check(c.x, m.x, fb);
                check(c.y, m.y, fb + 1);
            }
        }

        // ---- shift history, rotate, prefetch plane xp+2 ----
#pragma unroll
        for (int r = 0; r < 4; r++) {
            ymA[r] = ymB[r];
            ymB[r] = ymC[r];
            rawc[r] = cur[r + 1];
        }
#pragma unroll
        for (int r = 0; r < 6; r++) cur[r] = nxt[r];
#pragma unroll
        for (int r = 0; r < 6; r++) nxt[r] = loadrow(xp + 2, y0 - 1 + r);
    }

    __syncthreads();
    // Cold merge: sorted -> early-out once a key is rejected.
#pragma unroll
    for (int i = 0; i < KTOP; i++) {
        ull key = t[i];
        if (!key || !insert_topk_sh(sTop, key)) break;
    }
    __syncthreads();
    if (tid < KTOP)
        gBlockTop[b][blockIdx.x][tid] = sTop[tid];
}

// One warp per batch: 10 rounds of warp-shuffle argmax over 160 keys.
__global__ __launch_bounds__(NB * 32)
void finalize_kernel(float* __restrict__ out) {
    const int b    = threadIdx.x >> 5;
    const int lane = threadIdx.x & 31;

    const ull* src = &gBlockTop[b][0][0];   // NBLK*KTOP = 160 keys
    ull r[5];
#pragma unroll
    for (int k = 0; k < 5; k++) r[k] = src[k * 32 + lane];

    float* o = out + (size_t)b * KTOP * 5;

#pragma unroll
    for (int round = 0; round < KTOP; round++) {
        ull m = r[0];
#pragma unroll
        for (int k = 1; k < 5; k++) if (r[k] > m) m = r[k];
#pragma unroll
        for (int off = 16; off > 0; off >>= 1) {
            ull s = __shfl_xor_sync(FULLM, m, off);
            if (s > m) m = s;
        }
        // invalidate winner (keys unique: encode voxel index)
#pragma unroll
        for (int k = 0; k < 5; k++) if (r[k] == m) r[k] = 0ULL;

        if (lane == 0) {
            float v = __uint_as_float((unsigned)(m >> 32));
            unsigned idx = ~(unsigned)(m & 0xFFFFFFFFull);
            int ix = (int)(idx / (DY * DZ));
            int iy = (int)((idx / DZ) % DY);
            int iz = (int)(idx % DZ);
            o[round * 5 + 0] = ((float)ix / 127.0f) * 8000.0f - 4000.0f;
            o[round * 5 + 1] = ((float)iy / 127.0f) * 8000.0f - 4000.0f;
            o[round * 5 + 2] = ((float)iz / 63.0f)  * 2000.0f - 700.0f;
            o[round * 5 + 3] = (v > 0.3f) ? 0.0f : -1.0f;
            o[round * 5 + 4] = v;
        }
    }
}

extern "C" void kernel_launch(void* const* d_in, const int* in_sizes, int n_in,
                              void* d_out, int out_size) {
    const float* in = (const float*)d_in[0];
    float* out = (float*)d_out;

    dim3 grid(NBLK, 1, NB);            // 512 blocks x 8 autonomous warps
    peaks_kernel<<<grid, 256>>>(in);
    finalize_kernel<<<1, NB * 32>>>(out);
}

// round 7
// speedup vs baseline: 3.1220x; 1.6278x over previous
#include <cuda_runtime.h>
#include <float.h>

#define NB   32
#define DX   128
#define DY   128
#define DZ   64
#define KTOP 10
#define NBLK 16          // blocks per batch (4 y-groups * 4 x-quarters)
#define CAP  65536       // candidate capacity per batch (~1.7x expected peaks)
#define FULLM 0xFFFFFFFFu

typedef unsigned long long ull;

__device__ ull      gCand[NB][CAP];
__device__ unsigned gCnt[NB];

__global__ void init_kernel() {
    if (threadIdx.x < NB) gCnt[threadIdx.x] = 0u;
}

__device__ __forceinline__ float2 fmax2(float2 a, float2 b) {
    return make_float2(fmaxf(a.x, b.x), fmaxf(a.y, b.y));
}

// Shared 10-slot replace-min insert via CAS. Returns false if rejected.
__device__ __forceinline__ bool insert_topk_sh(ull* slots, ull key) {
    for (;;) {
        int mi = 0;
        ull mv = slots[0];
#pragma unroll
        for (int i = 1; i < KTOP; i++) {
            ull v = slots[i];
            if (v < mv) { mv = v; mi = i; }
        }
        if (key <= mv) return false;
        if (atomicCAS(&slots[mi], mv, key) == mv) return true;
    }
}

__global__ __launch_bounds__(256, 2)
void peaks_kernel(const float* __restrict__ in) {
    __shared__ ull sbuf[8][192];      // per-warp candidate staging

    const int tid  = threadIdx.x;
    const int w    = tid >> 5;
    const int lane = tid & 31;        // z-pair: z = {2*lane, 2*lane+1}
    const unsigned ltmask = (1u << lane) - 1u;

    const int b  = blockIdx.z;
    const int xq = blockIdx.x >> 2;               // x-quarter 0..3
    const int yg = (blockIdx.x & 3) * 8 + w;      // y-group 0..31
    const int y0 = yg * 4;
    const int x0 = xq * 32;

    const float* base = in + (size_t)b * DX * DY * DZ + 2 * lane;

    const float2 NEG = make_float2(-FLT_MAX, -FLT_MAX);
    auto loadrow = [&](int xp, int gy) -> float2 {
        if (xp >= 0 && xp < DX && gy >= 0 && gy < DY)
            return *(const float2*)(base + ((size_t)xp * DY + gy) * DZ);
        return NEG;
    };

    float2 cur[6], nxt[6];
#pragma unroll
    for (int r = 0; r < 6; r++) cur[r] = loadrow(x0 - 1, y0 - 1 + r);
#pragma unroll
    for (int r = 0; r < 6; r++) nxt[r] = loadrow(x0,     y0 - 1 + r);

    float2 ymA[4], ymB[4], rawc[4];
#pragma unroll
    for (int r = 0; r < 4; r++) { ymA[r] = NEG; ymB[r] = NEG; rawc[r] = NEG; }

    unsigned wcnt = 0;                 // warp-uniform buffer count (register)

    auto flush = [&](unsigned thresh) {
        if (wcnt >= thresh && wcnt > 0) {
            unsigned gbase = 0;
            if (lane == 0) gbase = atomicAdd(&gCnt[b], wcnt);
            gbase = __shfl_sync(FULLM, gbase, 0);
            for (unsigned i = lane; i < wcnt; i += 32) {
                unsigned g = gbase + i;
                if (g < CAP) gCand[b][g] = sbuf[w][i];
            }
            wcnt = 0;
        }
    };

    auto emit = [&](bool pred, ull key) {
        unsigned mask = __ballot_sync(FULLM, pred);
        if (mask) {
            if (pred) sbuf[w][wcnt + __popc(mask & ltmask)] = key;
            wcnt += __popc(mask);
        }
    };

    for (int cnt = 0; cnt < 34; cnt++) {
        const int xp = x0 - 1 + cnt;   // plane held in cur

        // issue next plane's loads early (consumed as cur two iters later)
        float2 fresh[6];
#pragma unroll
        for (int r = 0; r < 6; r++) fresh[r] = loadrow(xp + 2, y0 - 1 + r);

        // ---- z-window max (shuffles for z-neighbors) ----
        float2 zm[6];
#pragma unroll
        for (int r = 0; r < 6; r++) {
            float2 c = cur[r];
            float lft = __shfl_up_sync(FULLM, c.y, 1);
            float rgt = __shfl_down_sync(FULLM, c.x, 1);
            if (lane == 0)  lft = -FLT_MAX;
            if (lane == 31) rgt = -FLT_MAX;
            zm[r].x = fmaxf(fmaxf(lft, c.x), c.y);
            zm[r].y = fmaxf(fmaxf(c.x, c.y), rgt);
        }
        // ---- y-window max for the 4 output rows ----
        float2 ymC[4];
#pragma unroll
        for (int r = 0; r < 4; r++)
            ymC[r] = fmax2(zm[r], fmax2(zm[r + 1], zm[r + 2]));

        // ---- output plane xc = xp-1: emit peak candidates ----
        if (cnt >= 2) {
            const int xc = xp - 1;
#pragma unroll
            for (int r = 0; r < 4; r++) {
                float2 m = fmax2(ymA[r], fmax2(ymB[r], ymC[r]));
                float2 c = rawc[r];
                const int gy = y0 + r;
                const unsigned fb = (unsigned)((xc * DY + gy) * DZ + 2 * lane);
                ull k0 = ((ull)__float_as_uint(c.x) << 32) | (ull)(~fb);
                ull k1 = ((ull)__float_as_uint(c.y) << 32) | (ull)(~(fb + 1));
                emit(c.x == m.x, k0);
                emit(c.y == m.y, k1);
            }
            flush(160);                // capacity 192, site adds <= 32
        }

        // ---- rotate ----
#pragma unroll
        for (int r = 0; r < 4; r++) {
            ymA[r] = ymB[r];
            ymB[r] = ymC[r];
            rawc[r] = cur[r + 1];
        }
#pragma unroll
        for (int r = 0; r < 6; r++) cur[r] = nxt[r];
#pragma unroll
        for (int r = 0; r < 6; r++) nxt[r] = fresh[r];
    }

    flush(1);                          // tail flush
}

// One block per batch: top-10 over that batch's candidates.
__global__ __launch_bounds__(256)
void finalize_kernel(float* __restrict__ out) {
    __shared__ ull sTop[KTOP];

    const int b   = blockIdx.x;
    const int tid = threadIdx.x;
    if (tid < KTOP) sTop[tid] = 0ULL;
    __syncthreads();

    unsigned n = gCnt[b];
    if (n > CAP) n = CAP;

    // register sorted top-10 (descending)
    ull t[KTOP];
#pragma unroll
    for (int i = 0; i < KTOP; i++) t[i] = 0ULL;

    const ull* src = &gCand[b][0];
    for (unsigned i = tid; i < n; i += 256) {
        ull key = src[i];
        if (key > t[KTOP - 1]) {
            t[KTOP - 1] = key;
#pragma unroll
            for (int j = KTOP - 1; j > 0; j--) {
                ull a = t[j - 1], c = t[j];
                t[j - 1] = a > c ? a : c;
                t[j]     = a > c ? c : a;
            }
        }
    }

    // merge sorted lists into block top-10 (early-out on rejection)
#pragma unroll
    for (int i = 0; i < KTOP; i++) {
        ull key = t[i];
        if (!key || !insert_topk_sh(sTop, key)) break;
    }
    __syncthreads();

    if (tid < 32) {
        const int lane = tid;
        ull mine = (lane < KTOP) ? sTop[lane] : 0ULL;
        float* o = out + (size_t)b * KTOP * 5;
#pragma unroll
        for (int round = 0; round < KTOP; round++) {
            ull m = mine;
#pragma unroll
            for (int off = 16; off > 0; off >>= 1) {
                ull s = __shfl_xor_sync(FULLM, m, off);
                if (s > m) m = s;
            }
            if (mine == m) mine = 0ULL;    // keys unique (encode voxel index)
            if (lane == 0) {
                float v = __uint_as_float((unsigned)(m >> 32));
                unsigned idx = ~(unsigned)(m & 0xFFFFFFFFull);
                int ix = (int)(idx / (DY * DZ));
                int iy = (int)((idx / DZ) % DY);
                int iz = (int)(idx % DZ);
                o[round * 5 + 0] = ((float)ix / 127.0f) * 8000.0f - 4000.0f;
                o[round * 5 + 1] = ((float)iy / 127.0f) * 8000.0f - 4000.0f;
                o[round * 5 + 2] = ((float)iz / 63.0f)  * 2000.0f - 700.0f;
                o[round * 5 + 3] = (v > 0.3f) ? 0.0f : -1.0f;
                o[round * 5 + 4] = v;
            }
        }
    }
}

extern "C" void kernel_launch(void* const* d_in, const int* in_sizes, int n_in,
                              void* d_out, int out_size) {
    const float* in = (const float*)d_in[0];
    float* out = (float*)d_out;

    init_kernel<<<1, 32>>>();
    dim3 grid(NBLK, 1, NB);            // 512 blocks x 8 autonomous warps
    peaks_kernel<<<grid, 256>>>(in);
    finalize_kernel<<<NB, 256>>>(out);
}

// round 8
// speedup vs baseline: 3.2287x; 1.0342x over previous
#include <cuda_runtime.h>
#include <float.h>

#define NB   32
#define DX   128
#define DY   128
#define DZ   64
#define KTOP 10
#define NBLK 16          // blocks per batch (4 y-groups * 4 x-quarters)
#define CAP  65536
#define FULLM 0xFFFFFFFFu

typedef unsigned long long ull;

__device__ ull      gCand[NB][CAP];
__device__ unsigned gCnt[NB];        // zero-init; finalize re-zeroes each launch

__device__ __forceinline__ float2 fmax2(float2 a, float2 b) {
    return make_float2(fmaxf(a.x, b.x), fmaxf(a.y, b.y));
}

// Shared 10-slot replace-min insert via CAS. Returns false if rejected.
__device__ __forceinline__ bool insert_topk_sh(ull* slots, ull key) {
    for (;;) {
        int mi = 0;
        ull mv = slots[0];
#pragma unroll
        for (int i = 1; i < KTOP; i++) {
            ull v = slots[i];
            if (v < mv) { mv = v; mi = i; }
        }
        if (key <= mv) return false;
        if (atomicCAS(&slots[mi], mv, key) == mv) return true;
    }
}

__global__ __launch_bounds__(256, 2)
void peaks_kernel(const float* __restrict__ in) {
    __shared__ ull sbuf[8][192];      // per-warp candidate staging

    const int tid  = threadIdx.x;
    const int w    = tid >> 5;
    const int lane = tid & 31;        // z-pair: z = {2*lane, 2*lane+1}
    const unsigned ltmask = (1u << lane) - 1u;

    const int b  = blockIdx.z;
    const int xq = blockIdx.x >> 2;               // x-quarter 0..3
    const int yg = (blockIdx.x & 3) * 8 + w;      // y-group 0..31
    const int y0 = yg * 4;
    const int x0 = xq * 32;

    const float* base = in + (size_t)b * DX * DY * DZ + 2 * lane;

    const float2 NEG = make_float2(-FLT_MAX, -FLT_MAX);
    auto loadrow = [&](int xp, int gy) -> float2 {
        if (xp >= 0 && xp < DX && gy >= 0 && gy < DY)
            return *(const float2*)(base + ((size_t)xp * DY + gy) * DZ);
        return NEG;
    };

    float2 S0[6], S1[6], S2[6], S3[6];          // static plane ring
    float2 ymA[4], ymB[4];
#pragma unroll
    for (int r = 0; r < 4; r++) { ymA[r] = NEG; ymB[r] = NEG; }

    unsigned wcnt = 0;

    auto flush = [&](unsigned thresh) {
        if (wcnt >= thresh && wcnt > 0) {
            unsigned gbase = 0;
            if (lane == 0) gbase = atomicAdd(&gCnt[b], wcnt);
            gbase = __shfl_sync(FULLM, gbase, 0);
            for (unsigned i = lane; i < wcnt; i += 32) {
                unsigned g = gbase + i;
                if (g < CAP) gCand[b][g] = sbuf[w][i];
            }
            wcnt = 0;
        }
    };

    auto emit = [&](bool pred, ull key) {
        unsigned mask = __ballot_sync(FULLM, pred);
        if (mask) {
            if (pred) sbuf[w][wcnt + __popc(mask & ltmask)] = key;
            wcnt += __popc(mask);
        }
    };

    // one pipeline step at plane xp (in CUR): prefetch xp+2 into NXT,
    // z+y max from CUR, emit for plane xp-1 using PRV raw centers.
#define PSTEP(CUR, PRV, NXT, XP, DOLOAD, DOEMIT)                               \
    {                                                                          \
        const int xp = (XP);                                                   \
        if (DOLOAD) {                                                          \
            _Pragma("unroll")                                                  \
            for (int r = 0; r < 6; r++) NXT[r] = loadrow(xp + 2, y0 - 1 + r);  \
        }                                                                      \
        float2 zm[6];                                                          \
        _Pragma("unroll")                                                      \
        for (int r = 0; r < 6; r++) {                                          \
            float2 c = CUR[r];                                                 \
            float lft = __shfl_up_sync(FULLM, c.y, 1);                         \
            float rgt = __shfl_down_sync(FULLM, c.x, 1);                       \
            if (lane == 0)  lft = -FLT_MAX;                                    \
            if (lane == 31) rgt = -FLT_MAX;                                    \
            zm[r].x = fmaxf(fmaxf(lft, c.x), c.y);                             \
            zm[r].y = fmaxf(fmaxf(c.x, c.y), rgt);                             \
        }                                                                      \
        float2 ymC[4];                                                         \
        _Pragma("unroll")                                                      \
        for (int r = 0; r < 4; r++)                                            \
            ymC[r] = fmax2(zm[r], fmax2(zm[r + 1], zm[r + 2]));                \
        if (DOEMIT) {                                                          \
            const int xc = xp - 1;                                             \
            _Pragma("unroll")                                                  \
            for (int r = 0; r < 4; r++) {                                      \
                float2 m = fmax2(ymA[r], fmax2(ymB[r], ymC[r]));               \
                float2 c = PRV[r + 1];                                         \
                const unsigned fb =                                            \
                    (unsigned)((xc * DY + (y0 + r)) * DZ + 2 * lane);          \
                ull k0 = ((ull)__float_as_uint(c.x) << 32) | (ull)(~fb);       \
                ull k1 = ((ull)__float_as_uint(c.y) << 32) | (ull)(~(fb + 1)); \
                emit(c.x == m.x, k0);                                          \
                emit(c.y == m.y, k1);                                          \
            }                                                                  \
            flush(160);                                                        \
        }                                                                      \
        _Pragma("unroll")                                                      \
        for (int r = 0; r < 4; r++) { ymA[r] = ymB[r]; ymB[r] = ymC[r]; }      \
    }

#pragma unroll
    for (int r = 0; r < 6; r++) S0[r] = loadrow(x0 - 1, y0 - 1 + r);
#pragma unroll
    for (int r = 0; r < 6; r++) S1[r] = loadrow(x0,     y0 - 1 + r);

    // peel: cnt = 0..3 (emit starts at cnt 2)
    PSTEP(S0, S3, S2, x0 - 1, true, false);
    PSTEP(S1, S0, S3, x0,     true, false);
    PSTEP(S2, S1, S0, x0 + 1, true, true);
    PSTEP(S3, S2, S1, x0 + 2, true, true);

    for (int cnt = 4; cnt < 32; cnt += 4) {
        const int xb = x0 - 1 + cnt;
        PSTEP(S0, S3, S2, xb,     true, true);
        PSTEP(S1, S0, S3, xb + 1, true, true);
        PSTEP(S2, S1, S0, xb + 2, true, true);
        PSTEP(S3, S2, S1, xb + 3, true, true);
    }
    // epilogue: cnt = 32, 33 (no prefetch)
    PSTEP(S0, S3, S2, x0 + 31, false, true);
    PSTEP(S1, S0, S3, x0 + 32, false, true);

#undef PSTEP

    flush(1);                          // tail flush
}

// One block per batch (1024 threads): top-10 over candidates, then reset count.
__global__ __launch_bounds__(1024)
void finalize_kernel(float* __restrict__ out) {
    __shared__ ull sTop[KTOP];

    const int b   = blockIdx.x;
    const int tid = threadIdx.x;
    if (tid < KTOP) sTop[tid] = 0ULL;

    unsigned n = gCnt[b];
    if (n > CAP) n = CAP;
    __syncthreads();                   // sTop init + all threads have read n
    if (tid == 0) gCnt[b] = 0u;        // reset for next launch / graph replay

    ull t[KTOP];
#pragma unroll
    for (int i = 0; i < KTOP; i++) t[i] = 0ULL;

    const ull* src = &gCand[b][0];
    for (unsigned i = tid; i < n; i += 1024) {
        ull key = src[i];
        if (key > t[KTOP - 1]) {
            t[KTOP - 1] = key;
#pragma unroll
            for (int j = KTOP - 1; j > 0; j--) {
                ull a = t[j - 1], c = t[j];
                t[j - 1] = a > c ? a : c;
                t[j]     = a > c ? c : a;
            }
        }
    }

#pragma unroll
    for (int i = 0; i < KTOP; i++) {
        ull key = t[i];
        if (!key || !insert_topk_sh(sTop, key)) break;
    }
    __syncthreads();

    if (tid < 32) {
        const int lane = tid;
        ull mine = (lane < KTOP) ? sTop[lane] : 0ULL;
        float* o = out + (size_t)b * KTOP * 5;
#pragma unroll
        for (int round = 0; round < KTOP; round++) {
            ull m = mine;
#pragma unroll
            for (int off = 16; off > 0; off >>= 1) {
                ull s = __shfl_xor_sync(FULLM, m, off);
                if (s > m) m = s;
            }
            if (mine == m) mine = 0ULL;    // keys unique (encode voxel index)
            if (lane == 0) {
                float v = __uint_as_float((unsigned)(m >> 32));
                unsigned idx = ~(unsigned)(m & 0xFFFFFFFFull);
                int ix = (int)(idx / (DY * DZ));
                int iy = (int)((idx / DZ) % DY);
                int iz = (int)(idx % DZ);
                o[round * 5 + 0] = ((float)ix / 127.0f) * 8000.0f - 4000.0f;
                o[round * 5 + 1] = ((float)iy / 127.0f) * 8000.0f - 4000.0f;
                o[round * 5 + 2] = ((float)iz / 63.0f)  * 2000.0f - 700.0f;
                o[round * 5 + 3] = (v > 0.3f) ? 0.0f : -1.0f;
                o[round * 5 + 4] = v;
            }
        }
    }
}

extern "C" void kernel_launch(void* const* d_in, const int* in_sizes, int n_in,
                              void* d_out, int out_size) {
    const float* in = (const float*)d_in[0];
    float* out = (float*)d_out;

    dim3 grid(NBLK, 1, NB);            // 512 blocks x 8 autonomous warps
    peaks_kernel<<<grid, 256>>>(in);
    finalize_kernel<<<NB, 1024>>>(out);
}